// round 1
// baseline (speedup 1.0000x reference)
#include <cuda_runtime.h>
#include <cstddef>

// Problem constants (match reference)
constexpr int BATCH = 32;
constexpr int SEQ   = 2048;
constexpr int V     = 500000;   // HASH_VOCAB
constexpr int D     = 128;      // EMBED_DIM
constexpr int BASE  = 257;
constexpr int NGRAMS = 6;       // n in {3,4,5,6,7,8}

// One warp per token: 32 lanes x float4 = 128 floats.
// Each lane redundantly computes the 6 hashes (pure register ALU; token loads
// are warp-uniform -> single broadcast sector each).
__global__ __launch_bounds__(256) void byte_embed_kernel(
    const int* __restrict__ tokens,      // (B, S) int32
    const float* __restrict__ tables,    // (6, V, D) fp32
    float* __restrict__ out)             // (B, S, D) fp32
{
    const int warp_global = (blockIdx.x * blockDim.x + threadIdx.x) >> 5;
    const int lane = threadIdx.x & 31;
    // grid is sized exactly: BATCH*SEQ warps
    const int b = warp_global >> 11;          // / SEQ (SEQ = 2048)
    const int s = warp_global & (SEQ - 1);

    const int* trow = tokens + (size_t)b * SEQ;

    // Trailing window x[s], x[s-1], ..., x[s-7]
    int t[8];
#pragma unroll
    for (int j = 0; j < 8; ++j) {
        t[j] = (s - j >= 0) ? __ldg(trow + (s - j)) : 0;
    }

    // Incremental rolling hashes. For ngram n (=j+1 after j steps):
    //   h_n = (h_{n-1} * 257 + x[s-(n-1)]) % V
    // Valid (per reference mask) only when s >= n-1, else index = raw byte.
    const int x0 = t[0];
    int h = x0;
    int idx[NGRAMS];
#pragma unroll
    for (int j = 1; j <= 7; ++j) {
        h = (h * BASE + t[j]) % V;   // < 257*V + 255 < 2^31, safe in int32
        if (j >= 2) {                // j = n-1 for n in {3..8}
            idx[j - 2] = (s >= j) ? h : x0;
        }
    }

    // Six independent float4 gathers (512B rows, warp-coalesced), then reduce.
    const float4* __restrict__ tb4 = reinterpret_cast<const float4*>(tables);
    float4 v[NGRAMS];
#pragma unroll
    for (int k = 0; k < NGRAMS; ++k) {
        size_t off = ((size_t)k * V + (size_t)idx[k]) * (D / 4) + lane;
        v[k] = __ldg(tb4 + off);
    }

    float4 acc = v[0];
#pragma unroll
    for (int k = 1; k < NGRAMS; ++k) {
        acc.x += v[k].x; acc.y += v[k].y; acc.z += v[k].z; acc.w += v[k].w;
    }
    const float inv = 1.0f / 6.0f;
    acc.x *= inv; acc.y *= inv; acc.z *= inv; acc.w *= inv;

    float4* o4 = reinterpret_cast<float4*>(out);
    o4[(size_t)warp_global * (D / 4) + lane] = acc;
}

extern "C" void kernel_launch(void* const* d_in, const int* in_sizes, int n_in,
                              void* d_out, int out_size)
{
    (void)in_sizes; (void)n_in; (void)out_size;
    const int*   tokens = (const int*)d_in[0];
    const float* tables = (const float*)d_in[1];
    float*       out    = (float*)d_out;

    // BATCH*SEQ warps = 65536 warps = 2,097,152 threads
    const int threads = 256;
    const int warps_needed = BATCH * SEQ;
    const int blocks = (warps_needed * 32) / threads;   // 8192
    byte_embed_kernel<<<blocks, threads>>>(tokens, tables, out);
}

// round 2
// speedup vs baseline: 1.0539x; 1.0539x over previous
#include <cuda_runtime.h>
#include <cstddef>

// Problem constants (match reference)
constexpr int BATCH  = 32;
constexpr int SEQ    = 2048;
constexpr int V      = 500000;   // HASH_VOCAB
constexpr int D      = 128;      // EMBED_DIM
constexpr int BASE   = 257;
constexpr int NGRAMS = 6;        // n in {3,4,5,6,7,8}

// One warp per token: 32 lanes x float4 = 128 floats per embedding row.
// Table gathers have ~zero reuse (393k random rows of 3M) -> stream them
// through L2 with evict-first (__ldcs). Output is write-once -> __stcs.
__global__ __launch_bounds__(256) void byte_embed_kernel(
    const int* __restrict__ tokens,      // (B, S) int32
    const float* __restrict__ tables,    // (6, V, D) fp32
    float* __restrict__ out)             // (B, S, D) fp32
{
    const int warp_global = (blockIdx.x * blockDim.x + threadIdx.x) >> 5;
    const int lane = threadIdx.x & 31;
    const int b = warp_global >> 11;          // / SEQ (SEQ = 2048)
    const int s = warp_global & (SEQ - 1);

    const int* trow = tokens + (size_t)b * SEQ;

    // Trailing window x[s], x[s-1], ..., x[s-7] (warp-uniform addresses,
    // token array is 256KB -> L2-resident and hot; use default caching).
    int t[8];
#pragma unroll
    for (int j = 0; j < 8; ++j) {
        t[j] = (s - j >= 0) ? __ldg(trow + (s - j)) : 0;
    }

    // Incremental rolling hashes. After j steps, h == hash for ngram n=j+1:
    //   h_n = (h_{n-1} * 257 + x[s-(n-1)]) % V
    // Per reference, valid only when s >= n-1; else index = raw byte.
    const int x0 = t[0];
    int h = x0;
    int idx[NGRAMS];
#pragma unroll
    for (int j = 1; j <= 7; ++j) {
        h = (h * BASE + t[j]) % V;   // < 257*V + 255 < 2^31, int32-safe
        if (j >= 2) {                // j = n-1 for n in {3..8}
            idx[j - 2] = (s >= j) ? h : x0;
        }
    }

    // Six independent float4 gathers (512B rows, warp-coalesced).
    // 32-bit intra-table offsets (idx*32 + lane < 16M) keep address math
    // in single-width IMAD; only the table-base add is 64-bit.
    float4 v[NGRAMS];
#pragma unroll
    for (int k = 0; k < NGRAMS; ++k) {
        const float4* base = reinterpret_cast<const float4*>(
            tables + (size_t)k * V * D);
        unsigned off = (unsigned)idx[k] * (D / 4) + (unsigned)lane;
        v[k] = __ldcs(base + off);   // evict-first: no L2 pollution
    }

    float4 acc = v[0];
#pragma unroll
    for (int k = 1; k < NGRAMS; ++k) {
        acc.x += v[k].x; acc.y += v[k].y; acc.z += v[k].z; acc.w += v[k].w;
    }
    const float inv = 1.0f / 6.0f;
    acc.x *= inv; acc.y *= inv; acc.z *= inv; acc.w *= inv;

    float4* o4 = reinterpret_cast<float4*>(out);
    __stcs(o4 + (size_t)warp_global * (D / 4) + lane, acc);
}

extern "C" void kernel_launch(void* const* d_in, const int* in_sizes, int n_in,
                              void* d_out, int out_size)
{
    (void)in_sizes; (void)n_in; (void)out_size;
    const int*   tokens = (const int*)d_in[0];
    const float* tables = (const float*)d_in[1];
    float*       out    = (float*)d_out;

    const int threads = 256;
    const int warps_needed = BATCH * SEQ;           // 65536 warps
    const int blocks = (warps_needed * 32) / threads; // 8192
    byte_embed_kernel<<<blocks, threads>>>(tokens, tables, out);
}